// round 6
// baseline (speedup 1.0000x reference)
#include <cuda_runtime.h>
#include <cstdint>

// IntensityTransformation: out_k[b,c,h,w] = tf_k[b,c, round(255*img[b,c,h,w])]
// B=8, C=3, H=W=1024, LUT=256. Output = concat(out1, out2, out3).
//
// R6: interleave the 3 LUTs as float4[256] in smem -> one LDS.128 per pixel
// (was 12 LDS.32 per float4-iter, ~3x bank-conflicted). Streaming cache hints
// on the 400MB stream; unroll x2 for front-batched LDG MLP.

static constexpr int B = 8;
static constexpr int C = 3;
static constexpr int PLANES = B * C;                 // 24
static constexpr long long PLANE = 1024LL * 1024LL;  // elements per plane
static constexpr int LUT = 256;

__global__ __launch_bounds__(256)
void intensity_lut_kernel(const float* __restrict__ img,
                          const float* __restrict__ tf1,
                          const float* __restrict__ tf2,
                          const float* __restrict__ tf3,
                          float* __restrict__ out)
{
    __shared__ float4 slut[LUT];   // {tf1[i], tf2[i], tf3[i], 0}

    const int plane = blockIdx.y;  // 0..23
    const int t = threadIdx.x;     // blockDim.x == 256

    slut[t] = make_float4(tf1[plane * LUT + t],
                          tf2[plane * LUT + t],
                          tf3[plane * LUT + t],
                          0.0f);
    __syncthreads();

    const long long base = (long long)plane * PLANE;
    const float4* __restrict__ in4 = reinterpret_cast<const float4*>(img + base);
    float4* __restrict__ o1 = reinterpret_cast<float4*>(out + base);
    float4* __restrict__ o2 = reinterpret_cast<float4*>(out + (long long)PLANES * PLANE + base);
    float4* __restrict__ o3 = reinterpret_cast<float4*>(out + 2LL * PLANES * PLANE + base);

    const int n4 = (int)(PLANE / 4);          // 262144 float4 per plane
    const int nthreads = gridDim.x * blockDim.x;

    // Unroll x2: each thread handles indices i and i + nthreads per step.
    int i = blockIdx.x * blockDim.x + t;
    const int step = 2 * nthreads;

    for (; i + nthreads < n4; i += step) {
        // Front-batch both global loads for MLP.
        float4 va = __ldcs(&in4[i]);
        float4 vb = __ldcs(&in4[i + nthreads]);

        int a0 = __float2int_rn(255.0f * va.x);
        int a1 = __float2int_rn(255.0f * va.y);
        int a2 = __float2int_rn(255.0f * va.z);
        int a3 = __float2int_rn(255.0f * va.w);
        int b0 = __float2int_rn(255.0f * vb.x);
        int b1 = __float2int_rn(255.0f * vb.y);
        int b2 = __float2int_rn(255.0f * vb.z);
        int b3 = __float2int_rn(255.0f * vb.w);

        float4 la0 = slut[a0], la1 = slut[a1], la2 = slut[a2], la3 = slut[a3];
        float4 lb0 = slut[b0], lb1 = slut[b1], lb2 = slut[b2], lb3 = slut[b3];

        __stcs(&o1[i],            make_float4(la0.x, la1.x, la2.x, la3.x));
        __stcs(&o2[i],            make_float4(la0.y, la1.y, la2.y, la3.y));
        __stcs(&o3[i],            make_float4(la0.z, la1.z, la2.z, la3.z));
        __stcs(&o1[i + nthreads], make_float4(lb0.x, lb1.x, lb2.x, lb3.x));
        __stcs(&o2[i + nthreads], make_float4(lb0.y, lb1.y, lb2.y, lb3.y));
        __stcs(&o3[i + nthreads], make_float4(lb0.z, lb1.z, lb2.z, lb3.z));
    }

    // Tail (at most one iteration per thread).
    for (; i < n4; i += nthreads) {
        float4 v = __ldcs(&in4[i]);
        int i0 = __float2int_rn(255.0f * v.x);
        int i1 = __float2int_rn(255.0f * v.y);
        int i2 = __float2int_rn(255.0f * v.z);
        int i3 = __float2int_rn(255.0f * v.w);
        float4 l0 = slut[i0], l1 = slut[i1], l2 = slut[i2], l3 = slut[i3];
        __stcs(&o1[i], make_float4(l0.x, l1.x, l2.x, l3.x));
        __stcs(&o2[i], make_float4(l0.y, l1.y, l2.y, l3.y));
        __stcs(&o3[i], make_float4(l0.z, l1.z, l2.z, l3.z));
    }
}

extern "C" void kernel_launch(void* const* d_in, const int* in_sizes, int n_in,
                              void* d_out, int out_size)
{
    const float* img = (const float*)d_in[0];
    const float* tf1 = (const float*)d_in[1];
    const float* tf2 = (const float*)d_in[2];
    const float* tf3 = (const float*)d_in[3];
    float* out = (float*)d_out;

    dim3 grid(128, PLANES);   // 3072 CTAs, ~20/SM
    dim3 block(256);
    intensity_lut_kernel<<<grid, block>>>(img, tf1, tf2, tf3, out);
}